// round 12
// baseline (speedup 1.0000x reference)
#include <cuda_runtime.h>
#include <cuda_fp16.h>
#include <cstdint>

#define NA      100000
#define NM      12
#define NROWS   (NA*NM)          // 1,200,000
#define OUTC    128
#define ATOMF   64
#define EDGEF   41
#define INF     169
#define PAD     132              // padded row stride (floats), K2a/K1 tiles
#define PAD2    100              // padded row stride (floats), K2b 96-row tile

// ---------------- device scratch (allocation-free: __device__ globals) ----------------
__device__ __half  g_P [(size_t)NA*128];         // self projection  [n][slot]  fp16 (25.6MB)
__device__ __half  g_Pn[(size_t)NA*128];         // nbr  projection  [n][slot]  fp16 (25.6MB)
__device__ float   g_s[(size_t)NA*64];           // nbr_sumed pre-BN2
__device__ double  g_sum1[128], g_sq1[128];
__device__ double  g_sum2[64],  g_sq2[64];

// ---------------- helpers ----------------
__device__ __forceinline__ unsigned long long pk(float lo, float hi) {
    unsigned long long r;
    asm("mov.b64 %0, {%1,%2};" : "=l"(r) : "f"(lo), "f"(hi));
    return r;
}
__device__ __forceinline__ float2 upk(unsigned long long v) {
    float lo, hi;
    asm("mov.b64 {%0,%1}, %2;" : "=f"(lo), "=f"(hi) : "l"(v));
    return make_float2(lo, hi);
}
// packed fp32x2 fma: d = a*b + d  (FFMA2 -> 2x fp32 FMA throughput on sm_103a)
__device__ __forceinline__ void ffma2(unsigned long long& d,
                                      unsigned long long a, unsigned long long b) {
    asm("fma.rn.f32x2 %0, %1, %2, %0;" : "+l"(d) : "l"(a), "l"(b));
}
// pack two fp32 into fp16x2 (lo = a, hi = b)
__device__ __forceinline__ unsigned int packh2(float a, float b) {
    unsigned int r;
    asm("cvt.rn.f16x2.f32 %0, %2, %1;" : "=r"(r) : "f"(a), "f"(b));
    return r;
}
__device__ __forceinline__ float2 unph2(unsigned int u) {
    __half2 h = *(__half2*)&u;
    return __half22float2(h);
}
__device__ __forceinline__ float softplusf(float x) {
    return fmaxf(x, 0.f) + __logf(1.f + __expf(-fabsf(x)));
}
__device__ __forceinline__ float sigmoidf_(float x) {
    return 1.f / (1.f + __expf(-x));
}

// ---------------- K0: zero stat accumulators (must run every graph replay) ----------------
__global__ void k0_zero() {
    int t = threadIdx.x;
    if (t < 128) { g_sum1[t] = 0.0; g_sq1[t] = 0.0; }
    if (t < 64)  { g_sum2[t] = 0.0; g_sq2[t] = 0.0; }
}

// ---------------- K1: per-atom projections P_self / P_nbr (fp16 output) ----------------
// tile: 128 atoms x 128 outputs. blockIdx.y: 0 -> self (W cols 0..63), 1 -> nbr (64..127)
// store permuted: dst[n*128 + tc*4 + j]   (slot = (o%32)*4 + o/32)
#define SMEM_K1 (64*128*8 + 64*PAD*4)
__global__ __launch_bounds__(256, 2) void k1_proj(const float* __restrict__ atom,
                                                  const float* __restrict__ fcw) {
    extern __shared__ unsigned long long sm_u64[];
    unsigned long long* W2 = sm_u64;                 // [64][128] splat-packed
    float* At = (float*)(W2 + 64*128);               // [64][PAD] transposed A tile
    const int tid = threadIdx.x;
    const int tc = tid & 31, tr = tid >> 5;
    const int wbase = blockIdx.y ? 64 : 0;
    const long rowbase = (long)blockIdx.x * 128;

    for (int i = tid; i < 64*128; i += 256) {
        int o = i >> 6, f = i & 63;
        float w = fcw[o*INF + wbase + f];
        W2[f*128 + o] = pk(w, w);
    }
    for (int i = tid; i < 128*64; i += 256) {
        int r = i >> 6, f = i & 63;
        long gr = rowbase + r;
        At[f*PAD + r] = (gr < NA) ? atom[gr*64 + f] : 0.f;
    }
    __syncthreads();

    unsigned long long acc[8][4];
#pragma unroll
    for (int rp = 0; rp < 8; rp++)
#pragma unroll
        for (int j = 0; j < 4; j++) acc[rp][j] = 0ull;

    const int myrow0 = tr * 16;
#pragma unroll 2
    for (int f = 0; f < 64; f++) {
        const unsigned long long* wrow = W2 + f*128;
        unsigned long long w[4];
#pragma unroll
        for (int j = 0; j < 4; j++) w[j] = wrow[tc + 32*j];
        const ulonglong2* av = (const ulonglong2*)(At + f*PAD + myrow0);
#pragma unroll
        for (int q = 0; q < 4; q++) {
            ulonglong2 a = av[q];
#pragma unroll
            for (int j = 0; j < 4; j++) {
                ffma2(acc[2*q  ][j], a.x, w[j]);
                ffma2(acc[2*q+1][j], a.y, w[j]);
            }
        }
    }

    __half* dst = blockIdx.y ? g_Pn : g_P;
#pragma unroll
    for (int rp = 0; rp < 8; rp++) {
        long r0 = rowbase + myrow0 + 2*rp;
        long r1 = r0 + 1;
        float2 v0 = upk(acc[rp][0]), v1 = upk(acc[rp][1]);
        float2 v2 = upk(acc[rp][2]), v3 = upk(acc[rp][3]);
        if (r0 < NA) {
            uint2 s; s.x = packh2(v0.x, v1.x); s.y = packh2(v2.x, v3.x);
            *(uint2*)(dst + r0*128 + tc*4) = s;
        }
        if (r1 < NA) {
            uint2 s; s.x = packh2(v0.y, v1.y); s.y = packh2(v2.y, v3.y);
            *(uint2*)(dst + r1*128 + tc*4) = s;
        }
    }
}

// ---------------- K2a: edge GEMM + gather -> BN1 stats ONLY (no gated store) ----------------
// gated[row][o] = P_self[n][o] + P_nbr[k][o] + E[row] @ W_edge[o]   (fc_b cancels under BN)
#define SMEM_K2A (41*128*8 + 41*PAD*4 + 8*128*4*2 + 128*4*2)
__global__ __launch_bounds__(256, 2) void k2a_stats(const float* __restrict__ nbr,
                                                    const int* __restrict__ idxv,
                                                    const float* __restrict__ fcw) {
    extern __shared__ unsigned long long sm_u64[];
    unsigned long long* W2 = sm_u64;                 // [41][128] splat-packed
    float* Et   = (float*)(W2 + 41*128);             // [41][PAD] transposed E tile
    float* sSum = Et + 41*PAD;                       // [8][128]
    float* sSq  = sSum + 8*128;                      // [8][128]
    int*   sK   = (int*)(sSq + 8*128);               // [128]
    int*   sN   = sK + 128;                          // [128]
    const int tid = threadIdx.x;
    const int tc = tid & 31, tr = tid >> 5;
    const long rowbase = (long)blockIdx.x * 128;

    for (int i = tid; i < 41*128; i += 256) {
        int o = i / 41, e = i - o*41;
        float w = fcw[o*INF + 128 + e];
        W2[e*128 + o] = pk(w, w);
    }
    for (int i = tid; i < 128*41; i += 256) {
        int r = i / 41, e = i - r*41;
        Et[e*PAD + r] = nbr[rowbase*41 + i];
    }
    if (tid < 128) {
        sK[tid] = idxv[rowbase + tid];
        sN[tid] = (int)((rowbase + tid) / 12);
    }
    __syncthreads();

    const int myrow0 = tr * 16;
    unsigned long long acc[8][4];
#pragma unroll
    for (int rp = 0; rp < 8; rp++) {
        int r0 = myrow0 + 2*rp, r1 = r0 + 1;
        uint2 us0 = *(const uint2*)(g_P  + (size_t)sN[r0]*128 + tc*4);
        uint2 uq0 = *(const uint2*)(g_Pn + (size_t)sK[r0]*128 + tc*4);
        uint2 us1 = *(const uint2*)(g_P  + (size_t)sN[r1]*128 + tc*4);
        uint2 uq1 = *(const uint2*)(g_Pn + (size_t)sK[r1]*128 + tc*4);
        float2 sA0 = unph2(us0.x), sB0 = unph2(us0.y);
        float2 qA0 = unph2(uq0.x), qB0 = unph2(uq0.y);
        float2 sA1 = unph2(us1.x), sB1 = unph2(us1.y);
        float2 qA1 = unph2(uq1.x), qB1 = unph2(uq1.y);
        acc[rp][0] = pk(sA0.x + qA0.x, sA1.x + qA1.x);
        acc[rp][1] = pk(sA0.y + qA0.y, sA1.y + qA1.y);
        acc[rp][2] = pk(sB0.x + qB0.x, sB1.x + qB1.x);
        acc[rp][3] = pk(sB0.y + qB0.y, sB1.y + qB1.y);
    }

#pragma unroll 2
    for (int e = 0; e < 41; e++) {
        const unsigned long long* wrow = W2 + e*128;
        unsigned long long w[4];
#pragma unroll
        for (int j = 0; j < 4; j++) w[j] = wrow[tc + 32*j];
        const ulonglong2* av = (const ulonglong2*)(Et + e*PAD + myrow0);
#pragma unroll
        for (int q = 0; q < 4; q++) {
            ulonglong2 a = av[q];
#pragma unroll
            for (int j = 0; j < 4; j++) {
                ffma2(acc[2*q  ][j], a.x, w[j]);
                ffma2(acc[2*q+1][j], a.y, w[j]);
            }
        }
    }

    float ps[4] = {0,0,0,0}, pq[4] = {0,0,0,0};
#pragma unroll
    for (int rp = 0; rp < 8; rp++) {
        float2 v0 = upk(acc[rp][0]), v1 = upk(acc[rp][1]);
        float2 v2 = upk(acc[rp][2]), v3 = upk(acc[rp][3]);
        ps[0] += v0.x + v0.y;  pq[0] += v0.x*v0.x + v0.y*v0.y;
        ps[1] += v1.x + v1.y;  pq[1] += v1.x*v1.x + v1.y*v1.y;
        ps[2] += v2.x + v2.y;  pq[2] += v2.x*v2.x + v2.y*v2.y;
        ps[3] += v3.x + v3.y;  pq[3] += v3.x*v3.x + v3.y*v3.y;
    }
#pragma unroll
    for (int j = 0; j < 4; j++) {
        int o = tc + 32*j;                 // true channel index
        sSum[tr*128 + o] = ps[j];
        sSq [tr*128 + o] = pq[j];
    }
    __syncthreads();
    if (tid < 128) {
        float s = 0.f, q = 0.f;
#pragma unroll
        for (int t = 0; t < 8; t++) { s += sSum[t*128 + tid]; q += sSq[t*128 + tid]; }
        atomicAdd(&g_sum1[tid], (double)s);
        atomicAdd(&g_sq1 [tid], (double)q);
    }
}

// ---------------- K2b: recompute GEMM + BN1 + sig*softplus + m-sum -> g_s + BN2 stats ----------------
// tile: 96 rows = 8 atoms; warp tr owns atom blockIdx.x*8+tr (its 12 rows), lane tc owns
// channels tc (filter/core pair) and tc+32.
#define SMEM_K2B (41*128*8 + 41*PAD2*4 + 128*4*2 + 8*64*4 + 96*4)
__global__ __launch_bounds__(256, 2) void k2b_apply(const float* __restrict__ nbr,
                                                    const int* __restrict__ idxv,
                                                    const float* __restrict__ fcw,
                                                    const float* __restrict__ gam1,
                                                    const float* __restrict__ bet1) {
    extern __shared__ unsigned long long sm_u64[];
    unsigned long long* W2 = sm_u64;                 // [41][128] splat-packed
    float* Et     = (float*)(W2 + 41*128);           // [41][PAD2] transposed E tile (96 rows)
    float* sScale = Et + 41*PAD2;                    // [128] slot layout
    float* sShift = sScale + 128;                    // [128]
    float* sBuf   = sShift + 128;                    // [8][64] per-atom channel sums
    int*   sK     = (int*)(sBuf + 8*64);             // [96]
    const int tid = threadIdx.x;
    const int tc = tid & 31, tr = tid >> 5;
    const long rowbase = (long)blockIdx.x * 96;
    const int atom_n = blockIdx.x * 8 + tr;

    for (int i = tid; i < 41*128; i += 256) {
        int o = i / 41, e = i - o*41;
        float w = fcw[o*INF + 128 + e];
        W2[e*128 + o] = pk(w, w);
    }
    for (int i = tid; i < 96*41; i += 256) {
        int r = i / 41, e = i - r*41;
        Et[e*PAD2 + r] = nbr[rowbase*41 + i];
    }
    if (tid < 96) sK[tid] = idxv[rowbase + tid];
    if (tid < 128) {
        double mean = g_sum1[tid] / (double)NROWS;
        double var  = g_sq1[tid] / (double)NROWS - mean * mean;
        float scale = gam1[tid] * rsqrtf((float)var + 1e-5f);
        int slot = (tid & 31) * 4 + (tid >> 5);
        sScale[slot] = scale;
        sShift[slot] = bet1[tid] - (float)mean * scale;
    }
    __syncthreads();

    const int myrow0 = tr * 12;
    unsigned long long acc[6][4];
    {
        uint2 us = *(const uint2*)(g_P + (size_t)atom_n*128 + tc*4);   // self, same all rows
        float2 sA = unph2(us.x), sB = unph2(us.y);
#pragma unroll
        for (int rp = 0; rp < 6; rp++) {
            int r0 = myrow0 + 2*rp, r1 = r0 + 1;
            uint2 uq0 = *(const uint2*)(g_Pn + (size_t)sK[r0]*128 + tc*4);
            uint2 uq1 = *(const uint2*)(g_Pn + (size_t)sK[r1]*128 + tc*4);
            float2 qA0 = unph2(uq0.x), qB0 = unph2(uq0.y);
            float2 qA1 = unph2(uq1.x), qB1 = unph2(uq1.y);
            acc[rp][0] = pk(sA.x + qA0.x, sA.x + qA1.x);
            acc[rp][1] = pk(sA.y + qA0.y, sA.y + qA1.y);
            acc[rp][2] = pk(sB.x + qB0.x, sB.x + qB1.x);
            acc[rp][3] = pk(sB.y + qB0.y, sB.y + qB1.y);
        }
    }

#pragma unroll 2
    for (int e = 0; e < 41; e++) {
        const unsigned long long* wrow = W2 + e*128;
        unsigned long long w[4];
#pragma unroll
        for (int j = 0; j < 4; j++) w[j] = wrow[tc + 32*j];
        const ulonglong2* av = (const ulonglong2*)(Et + e*PAD2 + myrow0);
#pragma unroll
        for (int q = 0; q < 3; q++) {
            ulonglong2 a = av[q];
#pragma unroll
            for (int j = 0; j < 4; j++) {
                ffma2(acc[2*q  ][j], a.x, w[j]);
                ffma2(acc[2*q+1][j], a.y, w[j]);
            }
        }
    }

    // BN1 affine + sigmoid(filter)*softplus(core), summed over the atom's 12 rows
    float4 sc = *(const float4*)(sScale + tc*4);
    float4 sh = *(const float4*)(sShift + tc*4);
    float s0 = 0.f, s1 = 0.f;
#pragma unroll
    for (int rp = 0; rp < 6; rp++) {
        float2 v0 = upk(acc[rp][0]), v1 = upk(acc[rp][1]);
        float2 v2 = upk(acc[rp][2]), v3 = upk(acc[rp][3]);
        s0 += sigmoidf_(fmaf(v0.x, sc.x, sh.x)) * softplusf(fmaf(v2.x, sc.z, sh.z));
        s0 += sigmoidf_(fmaf(v0.y, sc.x, sh.x)) * softplusf(fmaf(v2.y, sc.z, sh.z));
        s1 += sigmoidf_(fmaf(v1.x, sc.y, sh.y)) * softplusf(fmaf(v3.x, sc.w, sh.w));
        s1 += sigmoidf_(fmaf(v1.y, sc.y, sh.y)) * softplusf(fmaf(v3.y, sc.w, sh.w));
    }
    g_s[(size_t)atom_n*64 + tc]      = s0;
    g_s[(size_t)atom_n*64 + 32 + tc] = s1;
    sBuf[tr*64 + tc]      = s0;
    sBuf[tr*64 + 32 + tc] = s1;
    __syncthreads();
    if (tid < 64) {
        float sum = 0.f, sq = 0.f;
#pragma unroll
        for (int t = 0; t < 8; t++) {
            float v = sBuf[t*64 + tid];
            sum += v; sq += v*v;
        }
        atomicAdd(&g_sum2[tid], (double)sum);
        atomicAdd(&g_sq2 [tid], (double)sq);
    }
}

// ---------------- K5: out = softplus(atom + BN2(nbr_sumed)), affine derived per-block ----------------
__global__ __launch_bounds__(256) void k5_out(const float* __restrict__ atom,
                                              const float* __restrict__ gam2,
                                              const float* __restrict__ bet2,
                                              float* __restrict__ out) {
    __shared__ float sSc[64], sSh[64];
    int tid = threadIdx.x;
    if (tid < 64) {
        double mean = g_sum2[tid] / (double)NA;
        double var  = g_sq2[tid] / (double)NA - mean * mean;
        float scale = gam2[tid] * rsqrtf((float)var + 1e-5f);
        sSc[tid] = scale;
        sSh[tid] = bet2[tid] - (float)mean * scale;
    }
    __syncthreads();
    int i = blockIdx.x * 256 + tid;             // one float4 group per thread
    int c4 = (i & 15) * 4;
    float4 a  = ((const float4*)atom)[i];
    float4 sv = ((const float4*)g_s)[i];
    float4 r;
    r.x = softplusf(a.x + fmaf(sv.x, sSc[c4+0], sSh[c4+0]));
    r.y = softplusf(a.y + fmaf(sv.y, sSc[c4+1], sSh[c4+1]));
    r.z = softplusf(a.z + fmaf(sv.z, sSc[c4+2], sSh[c4+2]));
    r.w = softplusf(a.w + fmaf(sv.w, sSc[c4+3], sSh[c4+3]));
    ((float4*)out)[i] = r;
}

// ---------------- launch ----------------
extern "C" void kernel_launch(void* const* d_in, const int* in_sizes, int n_in,
                              void* d_out, int out_size) {
    const float* atom = (const float*)d_in[0];   // [100000,64]
    const float* nbr  = (const float*)d_in[1];   // [100000,12,41]
    const int*   idxv = (const int*)  d_in[2];   // [100000,12]
    const float* fcw  = (const float*)d_in[3];   // [128,169]
    // d_in[4] = fc_b : cancels under BN1, unused
    const float* g1   = (const float*)d_in[5];
    const float* b1   = (const float*)d_in[6];
    const float* g2   = (const float*)d_in[7];
    const float* b2   = (const float*)d_in[8];
    float* out = (float*)d_out;

    cudaFuncSetAttribute(k1_proj,   cudaFuncAttributeMaxDynamicSharedMemorySize, SMEM_K1);
    cudaFuncSetAttribute(k2a_stats, cudaFuncAttributeMaxDynamicSharedMemorySize, SMEM_K2A);
    cudaFuncSetAttribute(k2b_apply, cudaFuncAttributeMaxDynamicSharedMemorySize, SMEM_K2B);

    k0_zero<<<1, 128>>>();
    dim3 gk1((NA + 127) / 128, 2);
    k1_proj  <<<gk1, 256, SMEM_K1>>>(atom, fcw);
    k2a_stats<<<NROWS / 128, 256, SMEM_K2A>>>(nbr, idxv, fcw);
    k2b_apply<<<NROWS / 96, 256, SMEM_K2B>>>(nbr, idxv, fcw, g1, b1);
    k5_out   <<<(NA * 64 / 4) / 256, 256>>>(atom, g2, b2, out);
}

// round 13
// speedup vs baseline: 1.7881x; 1.7881x over previous
#include <cuda_runtime.h>
#include <cuda_fp16.h>
#include <cstdint>

#define NA      100000
#define NM      12
#define NROWS   (NA*NM)          // 1,200,000
#define OUTC    128
#define ATOMF   64
#define EDGEF   41
#define INF     169
#define PAD     132              // padded row stride (floats) for transposed tiles

// ---------------- device scratch (allocation-free: __device__ globals) ----------------
__device__ __half  g_P [(size_t)NA*128];         // self projection  [n][slot]  fp16 (25.6MB)
__device__ __half  g_Pn[(size_t)NA*128];         // nbr  projection  [n][slot]  fp16 (25.6MB)
__device__ __half  g_gated[(size_t)NROWS*128];   // gated pre-BN     [row][slot] fp16 (307MB)
__device__ float   g_s[(size_t)NA*64];           // nbr_sumed pre-BN2
__device__ double  g_sum1[128], g_sq1[128];
__device__ double  g_sum2[64],  g_sq2[64];

// ---------------- helpers ----------------
__device__ __forceinline__ unsigned long long pk(float lo, float hi) {
    unsigned long long r;
    asm("mov.b64 %0, {%1,%2};" : "=l"(r) : "f"(lo), "f"(hi));
    return r;
}
__device__ __forceinline__ float2 upk(unsigned long long v) {
    float lo, hi;
    asm("mov.b64 {%0,%1}, %2;" : "=f"(lo), "=f"(hi) : "l"(v));
    return make_float2(lo, hi);
}
// packed fp32x2 fma: d = a*b + d
__device__ __forceinline__ void ffma2(unsigned long long& d,
                                      unsigned long long a, unsigned long long b) {
    asm("fma.rn.f32x2 %0, %1, %2, %0;" : "+l"(d) : "l"(a), "l"(b));
}
// pack two fp32 into fp16x2 (lo = a, hi = b)
__device__ __forceinline__ unsigned int packh2(float a, float b) {
    unsigned int r;
    asm("cvt.rn.f16x2.f32 %0, %2, %1;" : "=r"(r) : "f"(a), "f"(b));
    return r;
}
__device__ __forceinline__ float2 unph2(unsigned int u) {
    __half2 h = *(__half2*)&u;
    return __half22float2(h);
}
__device__ __forceinline__ float softplusf(float x) {
    return fmaxf(x, 0.f) + __logf(1.f + __expf(-fabsf(x)));
}
__device__ __forceinline__ float sigmoidf_(float x) {
    return __fdividef(1.f, 1.f + __expf(-x));
}

// ---------------- K0: zero stat accumulators (must run every graph replay) ----------------
__global__ void k0_zero() {
    int t = threadIdx.x;
    if (t < 128) { g_sum1[t] = 0.0; g_sq1[t] = 0.0; }
    if (t < 64)  { g_sum2[t] = 0.0; g_sq2[t] = 0.0; }
}

// ---------------- K1: per-atom projections (fp16 output), sel: 0 -> P_self, 1 -> P_nbr ----------------
// tile: 128 atoms x 128 outputs. store permuted: dst[n*128 + tc*4 + j]  (slot = (o%32)*4 + o/32)
#define SMEM_K1 (64*128*8 + 64*PAD*4)
__global__ __launch_bounds__(256, 2) void k1_proj(const float* __restrict__ atom,
                                                  const float* __restrict__ fcw,
                                                  int sel) {
    extern __shared__ unsigned long long sm_u64[];
    unsigned long long* W2 = sm_u64;                 // [64][128] splat-packed
    float* At = (float*)(W2 + 64*128);               // [64][PAD] transposed A tile
    const int tid = threadIdx.x;
    const int tc = tid & 31, tr = tid >> 5;
    const int wbase = sel ? 64 : 0;
    const long rowbase = (long)blockIdx.x * 128;

    for (int i = tid; i < 64*128; i += 256) {
        int o = i >> 6, f = i & 63;
        float w = fcw[o*INF + wbase + f];
        W2[f*128 + o] = pk(w, w);
    }
    for (int i = tid; i < 128*64; i += 256) {
        int r = i >> 6, f = i & 63;
        long gr = rowbase + r;
        At[f*PAD + r] = (gr < NA) ? atom[gr*64 + f] : 0.f;
    }
    __syncthreads();

    unsigned long long acc[8][4];
#pragma unroll
    for (int rp = 0; rp < 8; rp++)
#pragma unroll
        for (int j = 0; j < 4; j++) acc[rp][j] = 0ull;

    const int myrow0 = tr * 16;
#pragma unroll 2
    for (int f = 0; f < 64; f++) {
        const unsigned long long* wrow = W2 + f*128;
        unsigned long long w[4];
#pragma unroll
        for (int j = 0; j < 4; j++) w[j] = wrow[tc + 32*j];
        const ulonglong2* av = (const ulonglong2*)(At + f*PAD + myrow0);
#pragma unroll
        for (int q = 0; q < 4; q++) {
            ulonglong2 a = av[q];
#pragma unroll
            for (int j = 0; j < 4; j++) {
                ffma2(acc[2*q  ][j], a.x, w[j]);
                ffma2(acc[2*q+1][j], a.y, w[j]);
            }
        }
    }

    __half* dst = sel ? g_Pn : g_P;
#pragma unroll
    for (int rp = 0; rp < 8; rp++) {
        long r0 = rowbase + myrow0 + 2*rp;
        long r1 = r0 + 1;
        float2 v0 = upk(acc[rp][0]), v1 = upk(acc[rp][1]);
        float2 v2 = upk(acc[rp][2]), v3 = upk(acc[rp][3]);
        if (r0 < NA) {
            uint2 s; s.x = packh2(v0.x, v1.x); s.y = packh2(v2.x, v3.x);
            *(uint2*)(dst + r0*128 + tc*4) = s;
        }
        if (r1 < NA) {
            uint2 s; s.x = packh2(v0.y, v1.y); s.y = packh2(v2.y, v3.y);
            *(uint2*)(dst + r1*128 + tc*4) = s;
        }
    }
}

// ---------------- K2: edge GEMM + gather + gated store (fp16) + BN1 stats ----------------
// gated[row][o] = P_self[n][o] + P_nbr[k][o] + E[row] @ W_edge[o]   (fc_b cancels under BN)
// Gathers are issued FIRST (indices straight from idxv, warp-uniform) so their latency
// overlaps the smem tile fills + barrier.
#define SMEM_K2 (41*128*8 + 41*PAD*4 + 8*128*4*2)
__global__ __launch_bounds__(256, 2) void k2_gated(const float* __restrict__ nbr,
                                                   const int* __restrict__ idxv,
                                                   const float* __restrict__ fcw) {
    extern __shared__ unsigned long long sm_u64[];
    unsigned long long* W2 = sm_u64;                 // [41][128] splat-packed
    float* Et   = (float*)(W2 + 41*128);             // [41][PAD] transposed E tile
    float* sSum = Et + 41*PAD;                       // [8][128]
    float* sSq  = sSum + 8*128;                      // [8][128]
    const int tid = threadIdx.x;
    const int tc = tid & 31, tr = tid >> 5;
    const long rowbase = (long)blockIdx.x * 128;
    const int myrow0 = tr * 16;

    // --- acc init from gathers (issued before fills; overlaps with them) ---
    unsigned long long acc[8][4];
#pragma unroll
    for (int rp = 0; rp < 8; rp++) {
        int r0 = myrow0 + 2*rp, r1 = r0 + 1;
        int row0 = (int)rowbase + r0, row1 = (int)rowbase + r1;
        int n0 = row0 / 12, n1 = row1 / 12;          // warp-uniform
        int k0 = __ldg(&idxv[row0]), k1 = __ldg(&idxv[row1]);
        uint2 us0 = *(const uint2*)(g_P  + (size_t)n0*128 + tc*4);
        uint2 uq0 = *(const uint2*)(g_Pn + (size_t)k0*128 + tc*4);
        uint2 us1 = *(const uint2*)(g_P  + (size_t)n1*128 + tc*4);
        uint2 uq1 = *(const uint2*)(g_Pn + (size_t)k1*128 + tc*4);
        float2 sA0 = unph2(us0.x), sB0 = unph2(us0.y);
        float2 qA0 = unph2(uq0.x), qB0 = unph2(uq0.y);
        float2 sA1 = unph2(us1.x), sB1 = unph2(us1.y);
        float2 qA1 = unph2(uq1.x), qB1 = unph2(uq1.y);
        acc[rp][0] = pk(sA0.x + qA0.x, sA1.x + qA1.x);
        acc[rp][1] = pk(sA0.y + qA0.y, sA1.y + qA1.y);
        acc[rp][2] = pk(sB0.x + qB0.x, sB1.x + qB1.x);
        acc[rp][3] = pk(sB0.y + qB0.y, sB1.y + qB1.y);
    }

    // --- tile fills ---
    for (int i = tid; i < 41*128; i += 256) {
        int o = i / 41, e = i - o*41;
        float w = fcw[o*INF + 128 + e];
        W2[e*128 + o] = pk(w, w);
    }
    for (int i = tid; i < 128*41; i += 256) {
        int r = i / 41, e = i - r*41;
        Et[e*PAD + r] = nbr[rowbase*41 + i];
    }
    __syncthreads();

#pragma unroll 2
    for (int e = 0; e < 41; e++) {
        const unsigned long long* wrow = W2 + e*128;
        unsigned long long w[4];
#pragma unroll
        for (int j = 0; j < 4; j++) w[j] = wrow[tc + 32*j];
        const ulonglong2* av = (const ulonglong2*)(Et + e*PAD + myrow0);
#pragma unroll
        for (int q = 0; q < 4; q++) {
            ulonglong2 a = av[q];
#pragma unroll
            for (int j = 0; j < 4; j++) {
                ffma2(acc[2*q  ][j], a.x, w[j]);
                ffma2(acc[2*q+1][j], a.y, w[j]);
            }
        }
    }

    float ps[4] = {0,0,0,0}, pq[4] = {0,0,0,0};
#pragma unroll
    for (int rp = 0; rp < 8; rp++) {
        long r0 = rowbase + myrow0 + 2*rp, r1 = r0 + 1;
        float2 v0 = upk(acc[rp][0]), v1 = upk(acc[rp][1]);
        float2 v2 = upk(acc[rp][2]), v3 = upk(acc[rp][3]);
        uint2 h0; h0.x = packh2(v0.x, v1.x); h0.y = packh2(v2.x, v3.x);
        uint2 h1; h1.x = packh2(v0.y, v1.y); h1.y = packh2(v2.y, v3.y);
        *(uint2*)(g_gated + r0*128 + tc*4) = h0;
        *(uint2*)(g_gated + r1*128 + tc*4) = h1;
        ps[0] += v0.x + v0.y;  pq[0] += v0.x*v0.x + v0.y*v0.y;
        ps[1] += v1.x + v1.y;  pq[1] += v1.x*v1.x + v1.y*v1.y;
        ps[2] += v2.x + v2.y;  pq[2] += v2.x*v2.x + v2.y*v2.y;
        ps[3] += v3.x + v3.y;  pq[3] += v3.x*v3.x + v3.y*v3.y;
    }
#pragma unroll
    for (int j = 0; j < 4; j++) {
        int o = tc + 32*j;                 // true channel index
        sSum[tr*128 + o] = ps[j];
        sSq [tr*128 + o] = pq[j];
    }
    __syncthreads();
    if (tid < 128) {
        float s = 0.f, q = 0.f;
#pragma unroll
        for (int t = 0; t < 8; t++) { s += sSum[t*128 + tid]; q += sSq[t*128 + tid]; }
        atomicAdd(&g_sum1[tid], (double)s);
        atomicAdd(&g_sq1 [tid], (double)q);
    }
}

// ---------------- K4: BN1 affine + sig*softplus + sum over M + BN2 stats ----------------
// block 256 = 8 warps; warp handles atoms n0=blk*16+w and n1=n0+8 (2x ILP).
__global__ __launch_bounds__(256) void k4_reduce(const float* __restrict__ gam1,
                                                 const float* __restrict__ bet1) {
    __shared__ __align__(16) float sScale[128], sShift[128];
    __shared__ double sS[64], sQ[64];
    int tid = threadIdx.x;
    if (tid < 128) {
        double mean = g_sum1[tid] / (double)NROWS;
        double var  = g_sq1[tid] / (double)NROWS - mean * mean;
        float scale = gam1[tid] * rsqrtf((float)var + 1e-5f);
        float shift = bet1[tid] - (float)mean * scale;
        int slot = (tid & 31) * 4 + (tid >> 5);
        sScale[slot] = scale;
        sShift[slot] = shift;
    }
    if (tid < 64) { sS[tid] = 0.0; sQ[tid] = 0.0; }
    __syncthreads();

    int l = tid & 31, w = tid >> 5;
    long n0 = (long)blockIdx.x * 16 + w;
    long n1 = n0 + 8;
    float4 sc = *(const float4*)(sScale + l*4);
    float4 sh = *(const float4*)(sShift + l*4);
    float s0a = 0.f, s1a = 0.f, s0b = 0.f, s1b = 0.f;
    const __half* baseA = g_gated + n0 * 12 * 128 + l * 4;
    const __half* baseB = g_gated + n1 * 12 * 128 + l * 4;
#pragma unroll
    for (int m = 0; m < 12; m++) {
        uint2 ga = *(const uint2*)(baseA + (long)m*128);
        uint2 gb = *(const uint2*)(baseB + (long)m*128);
        float2 fa01 = unph2(ga.x), fa23 = unph2(ga.y);
        float2 fb01 = unph2(gb.x), fb23 = unph2(gb.y);
        s0a += sigmoidf_(fmaf(fa01.x, sc.x, sh.x)) * softplusf(fmaf(fa23.x, sc.z, sh.z));
        s1a += sigmoidf_(fmaf(fa01.y, sc.y, sh.y)) * softplusf(fmaf(fa23.y, sc.w, sh.w));
        s0b += sigmoidf_(fmaf(fb01.x, sc.x, sh.x)) * softplusf(fmaf(fb23.x, sc.z, sh.z));
        s1b += sigmoidf_(fmaf(fb01.y, sc.y, sh.y)) * softplusf(fmaf(fb23.y, sc.w, sh.w));
    }
    g_s[n0*64 + l]      = s0a;
    g_s[n0*64 + 32 + l] = s1a;
    g_s[n1*64 + l]      = s0b;
    g_s[n1*64 + 32 + l] = s1b;
    atomicAdd(&sS[l],      (double)(s0a + s0b));
    atomicAdd(&sQ[l],      (double)(s0a*s0a + s0b*s0b));
    atomicAdd(&sS[l + 32], (double)(s1a + s1b));
    atomicAdd(&sQ[l + 32], (double)(s1a*s1a + s1b*s1b));
    __syncthreads();
    if (tid < 64) {
        atomicAdd(&g_sum2[tid], sS[tid]);
        atomicAdd(&g_sq2 [tid], sQ[tid]);
    }
}

// ---------------- K5: out = softplus(atom + BN2(nbr_sumed)), affine derived per-block ----------------
__global__ __launch_bounds__(256) void k5_out(const float* __restrict__ atom,
                                              const float* __restrict__ gam2,
                                              const float* __restrict__ bet2,
                                              float* __restrict__ out) {
    __shared__ float sSc[64], sSh[64];
    int tid = threadIdx.x;
    if (tid < 64) {
        double mean = g_sum2[tid] / (double)NA;
        double var  = g_sq2[tid] / (double)NA - mean * mean;
        float scale = gam2[tid] * rsqrtf((float)var + 1e-5f);
        sSc[tid] = scale;
        sSh[tid] = bet2[tid] - (float)mean * scale;
    }
    __syncthreads();
    int i = blockIdx.x * 256 + tid;             // one float4 group per thread
    int c4 = (i & 15) * 4;
    float4 a  = ((const float4*)atom)[i];
    float4 sv = ((const float4*)g_s)[i];
    float4 r;
    r.x = softplusf(a.x + fmaf(sv.x, sSc[c4+0], sSh[c4+0]));
    r.y = softplusf(a.y + fmaf(sv.y, sSc[c4+1], sSh[c4+1]));
    r.z = softplusf(a.z + fmaf(sv.z, sSc[c4+2], sSh[c4+2]));
    r.w = softplusf(a.w + fmaf(sv.w, sSc[c4+3], sSh[c4+3]));
    ((float4*)out)[i] = r;
}

// ---------------- launch ----------------
extern "C" void kernel_launch(void* const* d_in, const int* in_sizes, int n_in,
                              void* d_out, int out_size) {
    const float* atom = (const float*)d_in[0];   // [100000,64]
    const float* nbr  = (const float*)d_in[1];   // [100000,12,41]
    const int*   idxv = (const int*)  d_in[2];   // [100000,12]
    const float* fcw  = (const float*)d_in[3];   // [128,169]
    // d_in[4] = fc_b : cancels under BN1, unused
    const float* g1   = (const float*)d_in[5];
    const float* b1   = (const float*)d_in[6];
    const float* g2   = (const float*)d_in[7];
    const float* b2   = (const float*)d_in[8];
    float* out = (float*)d_out;

    cudaFuncSetAttribute(k1_proj,  cudaFuncAttributeMaxDynamicSharedMemorySize, SMEM_K1);
    cudaFuncSetAttribute(k2_gated, cudaFuncAttributeMaxDynamicSharedMemorySize, SMEM_K2);

    k0_zero<<<1, 128>>>();                                   // launch 1
    int gk1 = (NA + 127) / 128;
    k1_proj  <<<gk1, 256, SMEM_K1>>>(atom, fcw, 0);          // launch 2
    k1_proj  <<<gk1, 256, SMEM_K1>>>(atom, fcw, 1);          // launch 3
    k2_gated <<<NROWS / 128, 256, SMEM_K2>>>(nbr, idxv, fcw);// launch 4  <- ncu capture slot
    k4_reduce<<<NA / 16, 256>>>(g1, b1);                     // launch 5
    k5_out   <<<(NA * 64 / 4) / 256, 256>>>(atom, g2, b2, out); // launch 6
}

// round 14
// speedup vs baseline: 2.2342x; 1.2495x over previous
#include <cuda_runtime.h>
#include <cuda_fp16.h>
#include <cstdint>

#define NA      100000
#define NM      12
#define NROWS   (NA*NM)          // 1,200,000
#define OUTC    128
#define ATOMF   64
#define EDGEF   41
#define INF     169
#define PAD     132              // padded row stride (floats) for transposed tiles

// ---------------- device scratch (allocation-free: __device__ globals) ----------------
__device__ __half  g_P [(size_t)NA*128];         // self projection  [n][slot]  fp16 (25.6MB)
__device__ __half  g_Pn[(size_t)NA*128];         // nbr  projection  [n][slot]  fp16 (25.6MB)
__device__ __half  g_gated[(size_t)NROWS*128];   // gated pre-BN     [row][slot] fp16 (307MB)
__device__ float   g_s[(size_t)NA*64];           // nbr_sumed pre-BN2
__device__ double  g_sum1[128], g_sq1[128];
__device__ double  g_sum2[64],  g_sq2[64];

// ---------------- helpers ----------------
__device__ __forceinline__ unsigned long long pk(float lo, float hi) {
    unsigned long long r;
    asm("mov.b64 %0, {%1,%2};" : "=l"(r) : "f"(lo), "f"(hi));
    return r;
}
__device__ __forceinline__ float2 upk(unsigned long long v) {
    float lo, hi;
    asm("mov.b64 {%0,%1}, %2;" : "=f"(lo), "=f"(hi) : "l"(v));
    return make_float2(lo, hi);
}
// packed fp32x2 fma: d = a*b + d
__device__ __forceinline__ void ffma2(unsigned long long& d,
                                      unsigned long long a, unsigned long long b) {
    asm("fma.rn.f32x2 %0, %1, %2, %0;" : "+l"(d) : "l"(a), "l"(b));
}
// pack two fp32 into fp16x2 (lo = a, hi = b)
__device__ __forceinline__ unsigned int packh2(float a, float b) {
    unsigned int r;
    asm("cvt.rn.f16x2.f32 %0, %2, %1;" : "=r"(r) : "f"(a), "f"(b));
    return r;
}
__device__ __forceinline__ float2 unph2(unsigned int u) {
    __half2 h = *(__half2*)&u;
    return __half22float2(h);
}
__device__ __forceinline__ float softplusf(float x) {
    return fmaxf(x, 0.f) + __logf(1.f + __expf(-fabsf(x)));
}
__device__ __forceinline__ float sigmoidf_(float x) {
    return __fdividef(1.f, 1.f + __expf(-x));
}

// ---------------- K0: zero stat accumulators (must run every graph replay) ----------------
__global__ void k0_zero() {
    int t = threadIdx.x;
    if (t < 128) { g_sum1[t] = 0.0; g_sq1[t] = 0.0; }
    if (t < 64)  { g_sum2[t] = 0.0; g_sq2[t] = 0.0; }
}

// ---------------- K1: per-atom projections (fp16 output), sel: 0 -> P_self, 1 -> P_nbr ----------------
// tile: 128 atoms x 128 outputs. W stored as plain fp32 in SLOT layout -> one LDS.128/thread/f.
// slot s <-> true channel o = (s>>2) + ((s&3)<<5);  thread tc owns slots 4tc..4tc+3 (o = tc+32j).
#define SMEM_K1 (64*128*4 + 64*PAD*4)
__global__ __launch_bounds__(256, 2) void k1_proj(const float* __restrict__ atom,
                                                  const float* __restrict__ fcw,
                                                  int sel) {
    extern __shared__ float sm_f[];
    float* Wf = sm_f;                                // [64][128] slot layout, plain fp32
    float* At = Wf + 64*128;                         // [64][PAD] transposed A tile
    const int tid = threadIdx.x;
    const int tc = tid & 31, tr = tid >> 5;
    const int wbase = sel ? 64 : 0;
    const long rowbase = (long)blockIdx.x * 128;

    for (int i = tid; i < 64*128; i += 256) {
        int f = i >> 7, s = i & 127;
        int o = (s >> 2) + ((s & 3) << 5);
        Wf[i] = fcw[o*INF + wbase + f];
    }
    for (int i = tid; i < 128*64; i += 256) {
        int r = i >> 6, f = i & 63;
        long gr = rowbase + r;
        At[f*PAD + r] = (gr < NA) ? atom[gr*64 + f] : 0.f;
    }
    __syncthreads();

    unsigned long long acc[8][4];
#pragma unroll
    for (int rp = 0; rp < 8; rp++)
#pragma unroll
        for (int j = 0; j < 4; j++) acc[rp][j] = 0ull;

    const int myrow0 = tr * 16;
#pragma unroll 2
    for (int f = 0; f < 64; f++) {
        float4 wf = *(const float4*)(Wf + f*128 + tc*4);
        unsigned long long w[4];
        w[0] = pk(wf.x, wf.x); w[1] = pk(wf.y, wf.y);
        w[2] = pk(wf.z, wf.z); w[3] = pk(wf.w, wf.w);
        const ulonglong2* av = (const ulonglong2*)(At + f*PAD + myrow0);
#pragma unroll
        for (int q = 0; q < 4; q++) {
            ulonglong2 a = av[q];
#pragma unroll
            for (int j = 0; j < 4; j++) {
                ffma2(acc[2*q  ][j], a.x, w[j]);
                ffma2(acc[2*q+1][j], a.y, w[j]);
            }
        }
    }

    // acc[rp][j] holds outputs for slot 4tc+j; store float4-per-row as fp16x4
    __half* dst = sel ? g_Pn : g_P;
#pragma unroll
    for (int rp = 0; rp < 8; rp++) {
        long r0 = rowbase + myrow0 + 2*rp;
        long r1 = r0 + 1;
        float2 v0 = upk(acc[rp][0]), v1 = upk(acc[rp][1]);
        float2 v2 = upk(acc[rp][2]), v3 = upk(acc[rp][3]);
        if (r0 < NA) {
            uint2 s; s.x = packh2(v0.x, v1.x); s.y = packh2(v2.x, v3.x);
            *(uint2*)(dst + r0*128 + tc*4) = s;
        }
        if (r1 < NA) {
            uint2 s; s.x = packh2(v0.y, v1.y); s.y = packh2(v2.y, v3.y);
            *(uint2*)(dst + r1*128 + tc*4) = s;
        }
    }
}

// ---------------- K2: edge GEMM + gather + gated store (fp16) + BN1 stats ----------------
// gated[row][o] = P_self[n][o] + P_nbr[k][o] + E[row] @ W_edge[o]   (fc_b cancels under BN)
// W as plain fp32 slot layout (1 LDS.128/thread/e + register splat); gathers issued first
// so their DRAM/L2 latency overlaps the smem tile fills + barrier.
#define SMEM_K2 (41*128*4 + 41*PAD*4 + 8*128*4*2)
__global__ __launch_bounds__(256, 2) void k2_gated(const float* __restrict__ nbr,
                                                   const int* __restrict__ idxv,
                                                   const float* __restrict__ fcw) {
    extern __shared__ float sm_f[];
    float* Wf   = sm_f;                              // [41][128] slot layout, plain fp32
    float* Et   = Wf + 41*128;                       // [41][PAD] transposed E tile
    float* sSum = Et + 41*PAD;                       // [8][128]
    float* sSq  = sSum + 8*128;                      // [8][128]
    const int tid = threadIdx.x;
    const int tc = tid & 31, tr = tid >> 5;
    const long rowbase = (long)blockIdx.x * 128;
    const int myrow0 = tr * 16;

    // --- acc init from gathers (issued before fills; overlaps with them) ---
    unsigned long long acc[8][4];
#pragma unroll
    for (int rp = 0; rp < 8; rp++) {
        int r0 = myrow0 + 2*rp, r1 = r0 + 1;
        int row0 = (int)rowbase + r0, row1 = (int)rowbase + r1;
        int n0 = row0 / 12, n1 = row1 / 12;          // warp-uniform
        int k0 = __ldg(&idxv[row0]), k1 = __ldg(&idxv[row1]);
        uint2 us0 = *(const uint2*)(g_P  + (size_t)n0*128 + tc*4);
        uint2 uq0 = *(const uint2*)(g_Pn + (size_t)k0*128 + tc*4);
        uint2 us1 = *(const uint2*)(g_P  + (size_t)n1*128 + tc*4);
        uint2 uq1 = *(const uint2*)(g_Pn + (size_t)k1*128 + tc*4);
        float2 sA0 = unph2(us0.x), sB0 = unph2(us0.y);
        float2 qA0 = unph2(uq0.x), qB0 = unph2(uq0.y);
        float2 sA1 = unph2(us1.x), sB1 = unph2(us1.y);
        float2 qA1 = unph2(uq1.x), qB1 = unph2(uq1.y);
        acc[rp][0] = pk(sA0.x + qA0.x, sA1.x + qA1.x);
        acc[rp][1] = pk(sA0.y + qA0.y, sA1.y + qA1.y);
        acc[rp][2] = pk(sB0.x + qB0.x, sB1.x + qB1.x);
        acc[rp][3] = pk(sB0.y + qB0.y, sB1.y + qB1.y);
    }

    // --- tile fills ---
    for (int i = tid; i < 41*128; i += 256) {
        int e = i >> 7, s = i & 127;
        int o = (s >> 2) + ((s & 3) << 5);
        Wf[i] = fcw[o*INF + 128 + e];
    }
    for (int i = tid; i < 128*41; i += 256) {
        int r = i / 41, e = i - r*41;
        Et[e*PAD + r] = nbr[rowbase*41 + i];
    }
    __syncthreads();

#pragma unroll 2
    for (int e = 0; e < 41; e++) {
        float4 wf = *(const float4*)(Wf + e*128 + tc*4);
        unsigned long long w[4];
        w[0] = pk(wf.x, wf.x); w[1] = pk(wf.y, wf.y);
        w[2] = pk(wf.z, wf.z); w[3] = pk(wf.w, wf.w);
        const ulonglong2* av = (const ulonglong2*)(Et + e*PAD + myrow0);
#pragma unroll
        for (int q = 0; q < 4; q++) {
            ulonglong2 a = av[q];
#pragma unroll
            for (int j = 0; j < 4; j++) {
                ffma2(acc[2*q  ][j], a.x, w[j]);
                ffma2(acc[2*q+1][j], a.y, w[j]);
            }
        }
    }

    float ps[4] = {0,0,0,0}, pq[4] = {0,0,0,0};
#pragma unroll
    for (int rp = 0; rp < 8; rp++) {
        long r0 = rowbase + myrow0 + 2*rp, r1 = r0 + 1;
        float2 v0 = upk(acc[rp][0]), v1 = upk(acc[rp][1]);
        float2 v2 = upk(acc[rp][2]), v3 = upk(acc[rp][3]);
        uint2 h0; h0.x = packh2(v0.x, v1.x); h0.y = packh2(v2.x, v3.x);
        uint2 h1; h1.x = packh2(v0.y, v1.y); h1.y = packh2(v2.y, v3.y);
        *(uint2*)(g_gated + r0*128 + tc*4) = h0;
        *(uint2*)(g_gated + r1*128 + tc*4) = h1;
        ps[0] += v0.x + v0.y;  pq[0] += v0.x*v0.x + v0.y*v0.y;
        ps[1] += v1.x + v1.y;  pq[1] += v1.x*v1.x + v1.y*v1.y;
        ps[2] += v2.x + v2.y;  pq[2] += v2.x*v2.x + v2.y*v2.y;
        ps[3] += v3.x + v3.y;  pq[3] += v3.x*v3.x + v3.y*v3.y;
    }
#pragma unroll
    for (int j = 0; j < 4; j++) {
        int o = tc + 32*j;                 // true channel index
        sSum[tr*128 + o] = ps[j];
        sSq [tr*128 + o] = pq[j];
    }
    __syncthreads();
    if (tid < 128) {
        float s = 0.f, q = 0.f;
#pragma unroll
        for (int t = 0; t < 8; t++) { s += sSum[t*128 + tid]; q += sSq[t*128 + tid]; }
        atomicAdd(&g_sum1[tid], (double)s);
        atomicAdd(&g_sq1 [tid], (double)q);
    }
}

// ---------------- K4: BN1 affine + sig*softplus + sum over M + BN2 stats ----------------
// block 256 = 8 warps; warp handles atoms n0=blk*16+w and n1=n0+8 (2x ILP).
__global__ __launch_bounds__(256) void k4_reduce(const float* __restrict__ gam1,
                                                 const float* __restrict__ bet1) {
    __shared__ __align__(16) float sScale[128], sShift[128];
    __shared__ double sS[64], sQ[64];
    int tid = threadIdx.x;
    if (tid < 128) {
        double mean = g_sum1[tid] / (double)NROWS;
        double var  = g_sq1[tid] / (double)NROWS - mean * mean;
        float scale = gam1[tid] * rsqrtf((float)var + 1e-5f);
        float shift = bet1[tid] - (float)mean * scale;
        int slot = (tid & 31) * 4 + (tid >> 5);
        sScale[slot] = scale;
        sShift[slot] = shift;
    }
    if (tid < 64) { sS[tid] = 0.0; sQ[tid] = 0.0; }
    __syncthreads();

    int l = tid & 31, w = tid >> 5;
    long n0 = (long)blockIdx.x * 16 + w;
    long n1 = n0 + 8;
    float4 sc = *(const float4*)(sScale + l*4);
    float4 sh = *(const float4*)(sShift + l*4);
    float s0a = 0.f, s1a = 0.f, s0b = 0.f, s1b = 0.f;
    const __half* baseA = g_gated + n0 * 12 * 128 + l * 4;
    const __half* baseB = g_gated + n1 * 12 * 128 + l * 4;
#pragma unroll
    for (int m = 0; m < 12; m++) {
        uint2 ga = *(const uint2*)(baseA + (long)m*128);
        uint2 gb = *(const uint2*)(baseB + (long)m*128);
        float2 fa01 = unph2(ga.x), fa23 = unph2(ga.y);
        float2 fb01 = unph2(gb.x), fb23 = unph2(gb.y);
        s0a += sigmoidf_(fmaf(fa01.x, sc.x, sh.x)) * softplusf(fmaf(fa23.x, sc.z, sh.z));
        s1a += sigmoidf_(fmaf(fa01.y, sc.y, sh.y)) * softplusf(fmaf(fa23.y, sc.w, sh.w));
        s0b += sigmoidf_(fmaf(fb01.x, sc.x, sh.x)) * softplusf(fmaf(fb23.x, sc.z, sh.z));
        s1b += sigmoidf_(fmaf(fb01.y, sc.y, sh.y)) * softplusf(fmaf(fb23.y, sc.w, sh.w));
    }
    g_s[n0*64 + l]      = s0a;
    g_s[n0*64 + 32 + l] = s1a;
    g_s[n1*64 + l]      = s0b;
    g_s[n1*64 + 32 + l] = s1b;
    atomicAdd(&sS[l],      (double)(s0a + s0b));
    atomicAdd(&sQ[l],      (double)(s0a*s0a + s0b*s0b));
    atomicAdd(&sS[l + 32], (double)(s1a + s1b));
    atomicAdd(&sQ[l + 32], (double)(s1a*s1a + s1b*s1b));
    __syncthreads();
    if (tid < 64) {
        atomicAdd(&g_sum2[tid], sS[tid]);
        atomicAdd(&g_sq2 [tid], sQ[tid]);
    }
}

// ---------------- K5: out = softplus(atom + BN2(nbr_sumed)), affine derived per-block ----------------
__global__ __launch_bounds__(256) void k5_out(const float* __restrict__ atom,
                                              const float* __restrict__ gam2,
                                              const float* __restrict__ bet2,
                                              float* __restrict__ out) {
    __shared__ float sSc[64], sSh[64];
    int tid = threadIdx.x;
    if (tid < 64) {
        double mean = g_sum2[tid] / (double)NA;
        double var  = g_sq2[tid] / (double)NA - mean * mean;
        float scale = gam2[tid] * rsqrtf((float)var + 1e-5f);
        sSc[tid] = scale;
        sSh[tid] = bet2[tid] - (float)mean * scale;
    }
    __syncthreads();
    int i = blockIdx.x * 256 + tid;             // one float4 group per thread
    int c4 = (i & 15) * 4;
    float4 a  = ((const float4*)atom)[i];
    float4 sv = ((const float4*)g_s)[i];
    float4 r;
    r.x = softplusf(a.x + fmaf(sv.x, sSc[c4+0], sSh[c4+0]));
    r.y = softplusf(a.y + fmaf(sv.y, sSc[c4+1], sSh[c4+1]));
    r.z = softplusf(a.z + fmaf(sv.z, sSc[c4+2], sSh[c4+2]));
    r.w = softplusf(a.w + fmaf(sv.w, sSc[c4+3], sSh[c4+3]));
    ((float4*)out)[i] = r;
}

// ---------------- launch ----------------
extern "C" void kernel_launch(void* const* d_in, const int* in_sizes, int n_in,
                              void* d_out, int out_size) {
    const float* atom = (const float*)d_in[0];   // [100000,64]
    const float* nbr  = (const float*)d_in[1];   // [100000,12,41]
    const int*   idxv = (const int*)  d_in[2];   // [100000,12]
    const float* fcw  = (const float*)d_in[3];   // [128,169]
    // d_in[4] = fc_b : cancels under BN1, unused
    const float* g1   = (const float*)d_in[5];
    const float* b1   = (const float*)d_in[6];
    const float* g2   = (const float*)d_in[7];
    const float* b2   = (const float*)d_in[8];
    float* out = (float*)d_out;

    cudaFuncSetAttribute(k1_proj,  cudaFuncAttributeMaxDynamicSharedMemorySize, SMEM_K1);
    cudaFuncSetAttribute(k2_gated, cudaFuncAttributeMaxDynamicSharedMemorySize, SMEM_K2);

    k0_zero<<<1, 128>>>();                                   // launch 1
    int gk1 = (NA + 127) / 128;
    k1_proj  <<<gk1, 256, SMEM_K1>>>(atom, fcw, 0);          // launch 2
    k1_proj  <<<gk1, 256, SMEM_K1>>>(atom, fcw, 1);          // launch 3
    k2_gated <<<NROWS / 128, 256, SMEM_K2>>>(nbr, idxv, fcw);// launch 4  <- ncu capture slot
    k4_reduce<<<NA / 16, 256>>>(g1, b1);                     // launch 5
    k5_out   <<<(NA * 64 / 4) / 256, 256>>>(atom, g2, b2, out); // launch 6
}

// round 15
// speedup vs baseline: 2.5178x; 1.1270x over previous
#include <cuda_runtime.h>
#include <cuda_fp16.h>
#include <cstdint>

#define NA      100000
#define NM      12
#define NROWS   (NA*NM)          // 1,200,000
#define INF     169
#define PAD     132              // padded row stride (floats) for K1 transposed tiles

// ---------------- device scratch (allocation-free: __device__ globals) ----------------
__device__ __half  g_P [(size_t)NA*128];         // self projection [n][o] natural fp16
__device__ __half  g_Pn[(size_t)NA*128];         // nbr  projection [n][o] natural fp16
__device__ __half  g_gated[(size_t)NROWS*128];   // gated pre-BN    [row][o] natural fp16 (307MB)
__device__ float   g_s[(size_t)NA*64];           // nbr_sumed pre-BN2 (natural)
__device__ double  g_sum1[128], g_sq1[128];
__device__ double  g_sum2[64],  g_sq2[64];

// ---------------- helpers ----------------
__device__ __forceinline__ unsigned long long pk(float lo, float hi) {
    unsigned long long r;
    asm("mov.b64 %0, {%1,%2};" : "=l"(r) : "f"(lo), "f"(hi));
    return r;
}
__device__ __forceinline__ float2 upk(unsigned long long v) {
    float lo, hi;
    asm("mov.b64 {%0,%1}, %2;" : "=f"(lo), "=f"(hi) : "l"(v));
    return make_float2(lo, hi);
}
__device__ __forceinline__ void ffma2(unsigned long long& d,
                                      unsigned long long a, unsigned long long b) {
    asm("fma.rn.f32x2 %0, %1, %2, %0;" : "+l"(d) : "l"(a), "l"(b));
}
__device__ __forceinline__ unsigned int packh2(float a, float b) {
    unsigned int r;
    asm("cvt.rn.f16x2.f32 %0, %2, %1;" : "=r"(r) : "f"(a), "f"(b));
    return r;
}
__device__ __forceinline__ float2 unph2(unsigned int u) {
    __half2 h = *(__half2*)&u;
    return __half22float2(h);
}
__device__ __forceinline__ float softplusf(float x) {
    return fmaxf(x, 0.f) + __logf(1.f + __expf(-fabsf(x)));
}
__device__ __forceinline__ float sigmoidf_(float x) {
    return __fdividef(1.f, 1.f + __expf(-x));
}
// m16n8k16 row.col f16 x f16 -> f32
__device__ __forceinline__ void mma16816(float& c0, float& c1, float& c2, float& c3,
                                         unsigned a0, unsigned a1, unsigned a2, unsigned a3,
                                         unsigned b0, unsigned b1) {
    asm volatile("mma.sync.aligned.m16n8k16.row.col.f32.f16.f16.f32 "
        "{%0,%1,%2,%3}, {%4,%5,%6,%7}, {%8,%9}, {%0,%1,%2,%3};"
        : "+f"(c0), "+f"(c1), "+f"(c2), "+f"(c3)
        : "r"(a0), "r"(a1), "r"(a2), "r"(a3), "r"(b0), "r"(b1));
}

// ---------------- K0: zero stat accumulators ----------------
__global__ void k0_zero() {
    int t = threadIdx.x;
    if (t < 128) { g_sum1[t] = 0.0; g_sq1[t] = 0.0; }
    if (t < 64)  { g_sum2[t] = 0.0; g_sq2[t] = 0.0; }
}

// ---------------- K1: per-atom projections (fp16, NATURAL layout) ----------------
// thread tc owns channels 4tc..4tc+3 for 16 rows (8 f32x2 row-pairs).
#define SMEM_K1 (64*128*4 + 64*PAD*4)
__global__ __launch_bounds__(256, 2) void k1_proj(const float* __restrict__ atom,
                                                  const float* __restrict__ fcw,
                                                  int sel) {
    extern __shared__ float sm_f[];
    float* Wf = sm_f;                                // [64][128] natural fp32
    float* At = Wf + 64*128;                         // [64][PAD] transposed A tile
    const int tid = threadIdx.x;
    const int tc = tid & 31, tr = tid >> 5;
    const int wbase = sel ? 64 : 0;
    const long rowbase = (long)blockIdx.x * 128;

    for (int i = tid; i < 64*128; i += 256) {
        int f = i >> 7, o = i & 127;
        Wf[i] = fcw[o*INF + wbase + f];
    }
    for (int i = tid; i < 128*64; i += 256) {
        int r = i >> 6, f = i & 63;
        long gr = rowbase + r;
        At[f*PAD + r] = (gr < NA) ? atom[gr*64 + f] : 0.f;
    }
    __syncthreads();

    unsigned long long acc[8][4];
#pragma unroll
    for (int rp = 0; rp < 8; rp++)
#pragma unroll
        for (int j = 0; j < 4; j++) acc[rp][j] = 0ull;

    const int myrow0 = tr * 16;
#pragma unroll 2
    for (int f = 0; f < 64; f++) {
        float4 wf = *(const float4*)(Wf + f*128 + tc*4);
        unsigned long long w[4];
        w[0] = pk(wf.x, wf.x); w[1] = pk(wf.y, wf.y);
        w[2] = pk(wf.z, wf.z); w[3] = pk(wf.w, wf.w);
        const ulonglong2* av = (const ulonglong2*)(At + f*PAD + myrow0);
#pragma unroll
        for (int q = 0; q < 4; q++) {
            ulonglong2 a = av[q];
#pragma unroll
            for (int j = 0; j < 4; j++) {
                ffma2(acc[2*q  ][j], a.x, w[j]);
                ffma2(acc[2*q+1][j], a.y, w[j]);
            }
        }
    }

    __half* dst = sel ? g_Pn : g_P;
#pragma unroll
    for (int rp = 0; rp < 8; rp++) {
        long r0 = rowbase + myrow0 + 2*rp;
        long r1 = r0 + 1;
        float2 v0 = upk(acc[rp][0]), v1 = upk(acc[rp][1]);
        float2 v2 = upk(acc[rp][2]), v3 = upk(acc[rp][3]);
        if (r0 < NA) {
            uint2 s; s.x = packh2(v0.x, v1.x); s.y = packh2(v2.x, v3.x);
            *(uint2*)(dst + r0*128 + tc*4) = s;   // channels 4tc..4tc+3
        }
        if (r1 < NA) {
            uint2 s; s.x = packh2(v0.y, v1.y); s.y = packh2(v2.y, v3.y);
            *(uint2*)(dst + r1*128 + tc*4) = s;
        }
    }
}

// ---------------- K2: tensor-core edge GEMM + gather + gated store + BN1 stats ----------------
// tile 128 rows x 128 cols, K=48 (41 padded). 8 warps, warp mg owns rows 16mg..16mg+15.
// smem: [0,12288)=EA frag u32[3072] -> reused as Cs u32[128][36];
//       [12288,24576)=raw E fp16[6144] -> reused as WB frag u32[3072];
//       [24576,26624)=sP/sQ f32[256] each.
#define SMEM_K2 (24576 + 2048)
__global__ __launch_bounds__(256, 2) void k2_gated(const float* __restrict__ nbr,
                                                   const int* __restrict__ idxv,
                                                   const float* __restrict__ fcw) {
    extern __shared__ unsigned int sm_u32[];
    unsigned int* EA = sm_u32;                       // frag E: [8mg][3kc][32l][4r]
    __half*       rawE = (__half*)(sm_u32 + 3072);   // [128][48]
    unsigned int* WB = sm_u32 + 3072;                // frag W: [3kc][8jp][32l][4r]
    unsigned int* Cs = sm_u32;                       // staged C: [128][36] u32
    float* sP = (float*)(sm_u32 + 6144);
    float* sQ = sP + 256;

    const int tid = threadIdx.x;
    const int tc = tid & 31, mg = tid >> 5;
    const int g = tc >> 2, t = tc & 3;
    const int rowbase = blockIdx.x * 128;

    const int R0 = rowbase + 16*mg + g;
    const int R1 = R0 + 8;
    const int n0 = R0 / 12, n1 = R1 / 12;
    const int kk0 = __ldg(&idxv[R0]), kk1 = __ldg(&idxv[R1]);

    // ---- stage raw E coalesced (fp16, zero-pad k 41..47) ----
#pragma unroll
    for (int ii = 0; ii < 24; ii++) {
        int i = tid + ii*256;                        // i < 6144
        int row = i / 48, k = i - (i/48)*48;
        float v = (k < 41) ? __ldg(&nbr[(size_t)(rowbase + row)*41 + k]) : 0.f;
        rawE[i] = __float2half_rn(v);
    }
    __syncthreads();
    // ---- build EA fragments from raw (linear i = ((m*3+kc)*32+l)*4+r) ----
#pragma unroll
    for (int ii = 0; ii < 12; ii++) {
        int i = tid + ii*256;                        // i < 3072
        int r = i & 3, l = (i >> 2) & 31, kc = (i >> 7) % 3, m = i / 384;
        int lg = l >> 2, lt = l & 3;
        int lr = 16*m + lg + (r & 1)*8;              // local row
        int k0 = 16*kc + 2*lt + (r >> 1)*8;          // even, <= 46
        EA[i] = *(const unsigned int*)(rawE + lr*48 + k0);
    }
    __syncthreads();                                 // raw dead; WB region free
    // ---- build WB fragments from gmem (i = ((kc*8+jp)*32+l)*4+r; r: {b0,b1}j, {b0,b1}j+1) ----
#pragma unroll
    for (int ii = 0; ii < 12; ii++) {
        int i = tid + ii*256;
        int r = i & 3, l = (i >> 2) & 31, jp = (i >> 7) & 7, kc = i >> 10;
        int lg = l >> 2, lt = l & 3;
        int j = jp*2 + (r >> 1);
        int o = 8*j + lg;
        int k0 = 16*kc + 2*lt + (r & 1)*8;
        float w0 = (k0   < 41) ? __ldg(&fcw[o*INF + 128 + k0  ]) : 0.f;
        float w1 = (k0+1 < 41) ? __ldg(&fcw[o*INF + 128 + k0+1]) : 0.f;
        WB[i] = packh2(w0, w1);
    }
    __syncthreads();

    // ---- MMA mainloop ----
    float c[16][4];
#pragma unroll
    for (int j = 0; j < 16; j++) { c[j][0] = c[j][1] = c[j][2] = c[j][3] = 0.f; }
#pragma unroll
    for (int kc = 0; kc < 3; kc++) {
        uint4 A = *(const uint4*)(EA + ((mg*3 + kc)*32 + tc)*4);
#pragma unroll
        for (int jp = 0; jp < 8; jp++) {
            uint4 B = *(const uint4*)(WB + ((kc*8 + jp)*32 + tc)*4);
            mma16816(c[2*jp  ][0], c[2*jp  ][1], c[2*jp  ][2], c[2*jp  ][3],
                     A.x, A.y, A.z, A.w, B.x, B.y);
            mma16816(c[2*jp+1][0], c[2*jp+1][1], c[2*jp+1][2], c[2*jp+1][3],
                     A.x, A.y, A.z, A.w, B.z, B.w);
        }
    }
    __syncthreads();                                 // EA/WB dead -> Cs reuse

    // ---- epilogue: +P gathers, stage, coalesced store, stats ----
    float myS0 = 0.f, myQ0 = 0.f, myS1 = 0.f, myQ1 = 0.f;
#pragma unroll
    for (int h = 0; h < 2; h++) {
        if (h) __syncthreads();                      // protect Cs/sP reuse
#pragma unroll
        for (int jj = 0; jj < 8; jj++) {
            int j = h*8 + jj;
            int o = 8*j + 2*t;
            float2 a0 = unph2(*(const unsigned int*)(g_P  + (size_t)n0 *128 + o));
            float2 b0 = unph2(*(const unsigned int*)(g_Pn + (size_t)kk0*128 + o));
            float2 a1 = unph2(*(const unsigned int*)(g_P  + (size_t)n1 *128 + o));
            float2 b1 = unph2(*(const unsigned int*)(g_Pn + (size_t)kk1*128 + o));
            int col = 4*jj + t;
            Cs[(16*mg + g    )*36 + col] = packh2(c[j][0] + a0.x + b0.x,
                                                  c[j][1] + a0.y + b0.y);
            Cs[(16*mg + g + 8)*36 + col] = packh2(c[j][2] + a1.x + b1.x,
                                                  c[j][3] + a1.y + b1.y);
        }
        __syncthreads();
        {   // coalesced store: 2 threads per row, 32 fp16 each
            int r = tid >> 1, seg = tid & 1;
            const unsigned int* src = Cs + r*36 + seg*16;
            __half* dstp = g_gated + (size_t)(rowbase + r)*128 + h*64 + seg*32;
            uint4 v0 = *(const uint4*)(src + 0);
            uint4 v1 = *(const uint4*)(src + 4);
            uint4 v2 = *(const uint4*)(src + 8);
            uint4 v3 = *(const uint4*)(src + 12);
            *(uint4*)(dstp +  0) = v0;
            *(uint4*)(dstp +  8) = v1;
            *(uint4*)(dstp + 16) = v2;
            *(uint4*)(dstp + 24) = v3;
        }
        {   // stats partials: 4 threads per channel, 32 rows each
            int ch = tid & 63, rq = tid >> 6;
            const __half* cs16 = (const __half*)Cs;  // row stride 72 fp16
            float s = 0.f, q = 0.f;
            for (int r2 = rq*32; r2 < rq*32 + 32; r2++) {
                float v = __half2float(cs16[r2*72 + ch]);
                s += v; q = fmaf(v, v, q);
            }
            sP[tid] = s; sQ[tid] = q;
        }
        __syncthreads();
        if (tid < 64) {
            float s = sP[tid] + sP[tid+64] + sP[tid+128] + sP[tid+192];
            float q = sQ[tid] + sQ[tid+64] + sQ[tid+128] + sQ[tid+192];
            if (h == 0) { myS0 = s; myQ0 = q; } else { myS1 = s; myQ1 = q; }
        }
    }
    if (tid < 64) {
        atomicAdd(&g_sum1[tid],      (double)myS0);
        atomicAdd(&g_sq1 [tid],      (double)myQ0);
        atomicAdd(&g_sum1[64 + tid], (double)myS1);
        atomicAdd(&g_sq1 [64 + tid], (double)myQ1);
    }
}

// ---------------- K4: BN1 affine + sig*softplus + sum over M + BN2 stats (natural layout) ----------------
__global__ __launch_bounds__(256) void k4_reduce(const float* __restrict__ gam1,
                                                 const float* __restrict__ bet1) {
    __shared__ __align__(8) float sScale[128], sShift[128];
    __shared__ double sS[64], sQ[64];
    int tid = threadIdx.x;
    if (tid < 128) {
        double mean = g_sum1[tid] / (double)NROWS;
        double var  = g_sq1[tid] / (double)NROWS - mean * mean;
        float scale = gam1[tid] * rsqrtf((float)var + 1e-5f);
        sScale[tid] = scale;
        sShift[tid] = bet1[tid] - (float)mean * scale;
    }
    if (tid < 64) { sS[tid] = 0.0; sQ[tid] = 0.0; }
    __syncthreads();

    int l = tid & 31, w = tid >> 5;
    long n0 = (long)blockIdx.x * 16 + w;
    long n1 = n0 + 8;
    float2 scf = *(const float2*)(sScale + 2*l);
    float2 shf = *(const float2*)(sShift + 2*l);
    float2 scc = *(const float2*)(sScale + 64 + 2*l);
    float2 shc = *(const float2*)(sShift + 64 + 2*l);
    float s0a = 0.f, s1a = 0.f, s0b = 0.f, s1b = 0.f;
    const __half* bA = g_gated + (size_t)n0 * 12 * 128;
    const __half* bB = g_gated + (size_t)n1 * 12 * 128;
#pragma unroll
    for (int m = 0; m < 12; m++) {
        float2 fa = unph2(*(const unsigned int*)(bA + m*128 + 2*l));
        float2 ca = unph2(*(const unsigned int*)(bA + m*128 + 64 + 2*l));
        float2 fb = unph2(*(const unsigned int*)(bB + m*128 + 2*l));
        float2 cb = unph2(*(const unsigned int*)(bB + m*128 + 64 + 2*l));
        s0a += sigmoidf_(fmaf(fa.x, scf.x, shf.x)) * softplusf(fmaf(ca.x, scc.x, shc.x));
        s1a += sigmoidf_(fmaf(fa.y, scf.y, shf.y)) * softplusf(fmaf(ca.y, scc.y, shc.y));
        s0b += sigmoidf_(fmaf(fb.x, scf.x, shf.x)) * softplusf(fmaf(cb.x, scc.x, shc.x));
        s1b += sigmoidf_(fmaf(fb.y, scf.y, shf.y)) * softplusf(fmaf(cb.y, scc.y, shc.y));
    }
    *(float2*)(g_s + (size_t)n0*64 + 2*l) = make_float2(s0a, s1a);
    *(float2*)(g_s + (size_t)n1*64 + 2*l) = make_float2(s0b, s1b);
    atomicAdd(&sS[2*l],     (double)(s0a + s0b));
    atomicAdd(&sQ[2*l],     (double)(s0a*s0a + s0b*s0b));
    atomicAdd(&sS[2*l + 1], (double)(s1a + s1b));
    atomicAdd(&sQ[2*l + 1], (double)(s1a*s1a + s1b*s1b));
    __syncthreads();
    if (tid < 64) {
        atomicAdd(&g_sum2[tid], sS[tid]);
        atomicAdd(&g_sq2 [tid], sQ[tid]);
    }
}

// ---------------- K5: out = softplus(atom + BN2(nbr_sumed)) ----------------
__global__ __launch_bounds__(256) void k5_out(const float* __restrict__ atom,
                                              const float* __restrict__ gam2,
                                              const float* __restrict__ bet2,
                                              float* __restrict__ out) {
    __shared__ float sSc[64], sSh[64];
    int tid = threadIdx.x;
    if (tid < 64) {
        double mean = g_sum2[tid] / (double)NA;
        double var  = g_sq2[tid] / (double)NA - mean * mean;
        float scale = gam2[tid] * rsqrtf((float)var + 1e-5f);
        sSc[tid] = scale;
        sSh[tid] = bet2[tid] - (float)mean * scale;
    }
    __syncthreads();
    int i = blockIdx.x * 256 + tid;
    int c4 = (i & 15) * 4;
    float4 a  = ((const float4*)atom)[i];
    float4 sv = ((const float4*)g_s)[i];
    float4 r;
    r.x = softplusf(a.x + fmaf(sv.x, sSc[c4+0], sSh[c4+0]));
    r.y = softplusf(a.y + fmaf(sv.y, sSc[c4+1], sSh[c4+1]));
    r.z = softplusf(a.z + fmaf(sv.z, sSc[c4+2], sSh[c4+2]));
    r.w = softplusf(a.w + fmaf(sv.w, sSc[c4+3], sSh[c4+3]));
    ((float4*)out)[i] = r;
}

// ---------------- launch ----------------
extern "C" void kernel_launch(void* const* d_in, const int* in_sizes, int n_in,
                              void* d_out, int out_size) {
    const float* atom = (const float*)d_in[0];   // [100000,64]
    const float* nbr  = (const float*)d_in[1];   // [100000,12,41]
    const int*   idxv = (const int*)  d_in[2];   // [100000,12]
    const float* fcw  = (const float*)d_in[3];   // [128,169]
    // d_in[4] = fc_b : cancels under BN1, unused
    const float* g1   = (const float*)d_in[5];
    const float* b1   = (const float*)d_in[6];
    const float* g2   = (const float*)d_in[7];
    const float* b2   = (const float*)d_in[8];
    float* out = (float*)d_out;

    cudaFuncSetAttribute(k1_proj, cudaFuncAttributeMaxDynamicSharedMemorySize, SMEM_K1);

    k0_zero<<<1, 128>>>();                                      // launch 1
    int gk1 = (NA + 127) / 128;
    k1_proj  <<<gk1, 256, SMEM_K1>>>(atom, fcw, 0);             // launch 2
    k1_proj  <<<gk1, 256, SMEM_K1>>>(atom, fcw, 1);             // launch 3
    k2_gated <<<NROWS / 128, 256, SMEM_K2>>>(nbr, idxv, fcw);   // launch 4 <- ncu slot
    k4_reduce<<<NA / 16, 256>>>(g1, b1);                        // launch 5
    k5_out   <<<(NA * 64 / 4) / 256, 256>>>(atom, g2, b2, out); // launch 6
}